// round 4
// baseline (speedup 1.0000x reference)
#include <cuda_runtime.h>
#include <cstdint>
#include <math.h>

#define T_DIRS 384   // num directions (both spaces)
#define N_PTS  384   // num points
#define RES    384   // resolution (thresholds)
#define D1     128
#define D2     32

// Scratch (no allocations allowed)
__device__ float g_v1[D1 * T_DIRS];
__device__ float g_v2[D2 * T_DIRS];
__device__ float g_nh1[N_PTS * T_DIRS];
__device__ float g_nh2[N_PTS * T_DIRS];
__device__ float g_partial[T_DIRS];

// ---------------- Threefry-2x32 (JAX), key = (0, 42) ----------------
__device__ __forceinline__ uint32_t rotl32(uint32_t x, int r) {
    return (x << r) | (x >> (32 - r));
}

__device__ __forceinline__ void threefry2x32_42(uint32_t c0, uint32_t c1,
                                                uint32_t& o0, uint32_t& o1) {
    const uint32_t k0 = 0u, k1 = 42u;
    const uint32_t k2 = 0x1BD11BDAu ^ k0 ^ k1;
    uint32_t x0 = c0 + k0, x1 = c1 + k1;
#define TF_GROUP(r0, r1, r2, r3, ka, kb, inc)                  \
    x0 += x1; x1 = rotl32(x1, r0); x1 ^= x0;                   \
    x0 += x1; x1 = rotl32(x1, r1); x1 ^= x0;                   \
    x0 += x1; x1 = rotl32(x1, r2); x1 ^= x0;                   \
    x0 += x1; x1 = rotl32(x1, r3); x1 ^= x0;                   \
    x0 += (ka); x1 += (kb) + (inc);
    TF_GROUP(13, 15, 26, 6,  k1, k2, 1u)
    TF_GROUP(17, 29, 16, 24, k2, k0, 2u)
    TF_GROUP(13, 15, 26, 6,  k0, k1, 3u)
    TF_GROUP(17, 29, 16, 24, k1, k2, 4u)
    TF_GROUP(13, 15, 26, 6,  k2, k0, 5u)
#undef TF_GROUP
    o0 = x0; o1 = x1;
}

// ---------------- XLA ErfInv (f32, Giles) ----------------
__device__ __forceinline__ float erfinv_xla(float x) {
    float w = -log1pf(-x * x);
    float p;
    if (w < 5.0f) {
        w -= 2.5f;
        p = 2.81022636e-08f;
        p = fmaf(p, w, 3.43273939e-07f);
        p = fmaf(p, w, -3.5233877e-06f);
        p = fmaf(p, w, -4.39150654e-06f);
        p = fmaf(p, w, 0.00021858087f);
        p = fmaf(p, w, -0.00125372503f);
        p = fmaf(p, w, -0.00417768164f);
        p = fmaf(p, w, 0.246640727f);
        p = fmaf(p, w, 1.50140941f);
    } else {
        w = sqrtf(w) - 3.0f;
        p = -0.000200214257f;
        p = fmaf(p, w, 0.000100950558f);
        p = fmaf(p, w, 0.00134934322f);
        p = fmaf(p, w, -0.00367342844f);
        p = fmaf(p, w, 0.00573950773f);
        p = fmaf(p, w, -0.0076224613f);
        p = fmaf(p, w, 0.00943887047f);
        p = fmaf(p, w, 1.00167406f);
        p = fmaf(p, w, 2.83297682f);
    }
    return p * x;
}

// Element j (row-major flat index) of jax.random.normal(key(42), shape),
// PARTITIONABLE threefry layout (modern JAX default):
//   counter = 64-bit j split as (hi, lo) = (0, j) for j < 2^32
//   bits = y0 ^ y1   (32-bit width XORs both threefry outputs)
__device__ __forceinline__ float jax_normal_elem(uint32_t j) {
    uint32_t o0, o1;
    threefry2x32_42(0u, j, o0, o1);
    uint32_t bits = o0 ^ o1;
    uint32_t fb = (bits >> 9) | 0x3f800000u;
    float f = __uint_as_float(fb) - 1.0f;          // [0, 1)
    const float lo = -0.99999994f;                  // nextafter(-1, 0)
    float u = f * 2.0f + lo;                        // (maxval-minval) rounds to 2.0f
    u = fmaxf(lo, u);
    return 1.41421356f * erfinv_xla(u);
}

// ---------------- Kernel 1: generate + normalize direction columns ----------------
// grid (T_DIRS, 2), block 128. y=0 -> v1 (d=128), y=1 -> v2 (d=32).
__global__ void gen_dirs_kernel() {
    int t = blockIdx.x;
    int i = threadIdx.x;
    int which = blockIdx.y;
    int d = which ? D2 : D1;
    float* out = which ? g_v2 : g_v1;

    float val = 0.0f;
    if (i < d) {
        uint32_t j = (uint32_t)(i * T_DIRS + t);   // row-major (d, T)
        val = jax_normal_elem(j);
    }

    __shared__ float sred[128];
    sred[i] = val * val;
    __syncthreads();
    for (int s = 64; s > 0; s >>= 1) {
        if (i < s) sred[i] += sred[i + s];
        __syncthreads();
    }
    float nrm = sqrtf(sred[0]);
    if (i < d) out[i * T_DIRS + t] = val / nrm;
}

// ---------------- Kernel 2: nh = x @ v  ([N,K] @ [K,T]) ----------------
// grid (T_DIRS/128, N_PTS), block 128. which: 0 -> space1, 1 -> space2.
__global__ void gemm_kernel(const float* __restrict__ x, int K, int which) {
    const float* __restrict__ v = which ? g_v2 : g_v1;
    float* __restrict__ nh = which ? g_nh2 : g_nh1;
    int t = blockIdx.x * 128 + threadIdx.x;
    int n = blockIdx.y;
    const float* xr = x + (size_t)n * K;
    float acc = 0.0f;
#pragma unroll 8
    for (int k = 0; k < K; ++k)
        acc = fmaf(__ldg(&xr[k]), v[k * T_DIRS + t], acc);
    nh[n * T_DIRS + t] = acc;
}

// ---------------- Kernel 3: fused ECT + squared-diff partial ----------------
// grid T_DIRS (one block per direction t), block RES threads (one per threshold r).
__global__ void ect_loss_kernel() {
    int t = blockIdx.x;
    int r = threadIdx.x;

    __shared__ float s1[N_PTS];
    __shared__ float s2[N_PTS];
    s1[r] = g_nh1[r * T_DIRS + t];   // r doubles as point index for the load
    s2[r] = g_nh2[r * T_DIRS + t];
    __syncthreads();

    float lin = (float)(-1.0 + 2.0 * (double)r / 383.0);
    float acc1 = 0.0f, acc2 = 0.0f;

#pragma unroll 4
    for (int n = 0; n < N_PTS; ++n) {
        float a1 = 500.0f * (lin - s1[n]);
        if (a1 > 20.0f)        acc1 += 1.0f;
        else if (a1 > -20.0f)  acc1 += 1.0f / (1.0f + expf(-a1));
        float a2 = 500.0f * (lin - s2[n]);
        if (a2 > 20.0f)        acc2 += 1.0f;
        else if (a2 > -20.0f)  acc2 += 1.0f / (1.0f + expf(-a2));
    }

    float d = acc1 - acc2;
    __shared__ float sred[RES];
    sred[r] = d * d;
    __syncthreads();
    if (r < 128) sred[r] += sred[r + 256];
    __syncthreads();
    for (int s = 128; s > 0; s >>= 1) {
        if (r < s) sred[r] += sred[r + s];
        __syncthreads();
    }
    if (r == 0) g_partial[t] = sred[0];
}

// ---------------- Kernel 4: final reduction -> loss ----------------
__global__ void final_kernel(float* __restrict__ out, int out_size) {
    int tid = threadIdx.x;
    __shared__ float sred[T_DIRS];
    sred[tid] = g_partial[tid];
    __syncthreads();
    if (tid < 128) sred[tid] += sred[tid + 256];
    __syncthreads();
    for (int s = 128; s > 0; s >>= 1) {
        if (tid < s) sred[tid] += sred[tid + s];
        __syncthreads();
    }
    // zero any extra output elements (out is poisoned)
    for (int idx = tid; idx < out_size; idx += blockDim.x)
        if (idx > 0) out[idx] = 0.0f;
    if (tid == 0) out[0] = sred[0] / (float)(RES * T_DIRS);
}

extern "C" void kernel_launch(void* const* d_in, const int* in_sizes, int n_in,
                              void* d_out, int out_size) {
    const float* space1;
    const float* space2;
    if (in_sizes[0] == N_PTS * D1) {
        space1 = (const float*)d_in[0];
        space2 = (const float*)d_in[1];
    } else {
        space1 = (const float*)d_in[1];
        space2 = (const float*)d_in[0];
    }
    float* out = (float*)d_out;

    gen_dirs_kernel<<<dim3(T_DIRS, 2), 128>>>();
    gemm_kernel<<<dim3(T_DIRS / 128, N_PTS), 128>>>(space1, D1, 0);
    gemm_kernel<<<dim3(T_DIRS / 128, N_PTS), 128>>>(space2, D2, 1);
    ect_loss_kernel<<<T_DIRS, RES>>>();
    final_kernel<<<1, T_DIRS>>>(out, out_size);
}

// round 7
// speedup vs baseline: 1.6137x; 1.6137x over previous
#include <cuda_runtime.h>
#include <cstdint>
#include <math.h>

#define T_DIRS 384   // num directions (both spaces)
#define N_PTS  384   // num points
#define RES    384   // resolution (thresholds)
#define D1     128
#define D2     32
#define SORT_N 512   // N_PTS padded to power of two
#define WIN    0.04f // 20/500: |arg|>20 -> sigmoid is 0/1 to 2e-9

// Scratch (no allocations allowed)
__device__ float g_v1[D1 * T_DIRS];
__device__ float g_v2[D2 * T_DIRS];
__device__ float g_nh1[N_PTS * T_DIRS];
__device__ float g_nh2[N_PTS * T_DIRS];
__device__ float g_partial[T_DIRS];

// ---------------- Threefry-2x32 (JAX), key = (0, 42) ----------------
__device__ __forceinline__ uint32_t rotl32(uint32_t x, int r) {
    return (x << r) | (x >> (32 - r));
}

__device__ __forceinline__ void threefry2x32_42(uint32_t c0, uint32_t c1,
                                                uint32_t& o0, uint32_t& o1) {
    const uint32_t k0 = 0u, k1 = 42u;
    const uint32_t k2 = 0x1BD11BDAu ^ k0 ^ k1;
    uint32_t x0 = c0 + k0, x1 = c1 + k1;
#define TF_GROUP(r0, r1, r2, r3, ka, kb, inc)                  \
    x0 += x1; x1 = rotl32(x1, r0); x1 ^= x0;                   \
    x0 += x1; x1 = rotl32(x1, r1); x1 ^= x0;                   \
    x0 += x1; x1 = rotl32(x1, r2); x1 ^= x0;                   \
    x0 += x1; x1 = rotl32(x1, r3); x1 ^= x0;                   \
    x0 += (ka); x1 += (kb) + (inc);
    TF_GROUP(13, 15, 26, 6,  k1, k2, 1u)
    TF_GROUP(17, 29, 16, 24, k2, k0, 2u)
    TF_GROUP(13, 15, 26, 6,  k0, k1, 3u)
    TF_GROUP(17, 29, 16, 24, k1, k2, 4u)
    TF_GROUP(13, 15, 26, 6,  k2, k0, 5u)
#undef TF_GROUP
    o0 = x0; o1 = x1;
}

// ---------------- XLA ErfInv (f32, Giles) ----------------
__device__ __forceinline__ float erfinv_xla(float x) {
    float w = -log1pf(-x * x);
    float p;
    if (w < 5.0f) {
        w -= 2.5f;
        p = 2.81022636e-08f;
        p = fmaf(p, w, 3.43273939e-07f);
        p = fmaf(p, w, -3.5233877e-06f);
        p = fmaf(p, w, -4.39150654e-06f);
        p = fmaf(p, w, 0.00021858087f);
        p = fmaf(p, w, -0.00125372503f);
        p = fmaf(p, w, -0.00417768164f);
        p = fmaf(p, w, 0.246640727f);
        p = fmaf(p, w, 1.50140941f);
    } else {
        w = sqrtf(w) - 3.0f;
        p = -0.000200214257f;
        p = fmaf(p, w, 0.000100950558f);
        p = fmaf(p, w, 0.00134934322f);
        p = fmaf(p, w, -0.00367342844f);
        p = fmaf(p, w, 0.00573950773f);
        p = fmaf(p, w, -0.0076224613f);
        p = fmaf(p, w, 0.00943887047f);
        p = fmaf(p, w, 1.00167406f);
        p = fmaf(p, w, 2.83297682f);
    }
    return p * x;
}

// Partitionable threefry layout: counter (0, j), 32-bit draw = y0 ^ y1.
__device__ __forceinline__ float jax_normal_elem(uint32_t j) {
    uint32_t o0, o1;
    threefry2x32_42(0u, j, o0, o1);
    uint32_t bits = o0 ^ o1;
    uint32_t fb = (bits >> 9) | 0x3f800000u;
    float f = __uint_as_float(fb) - 1.0f;          // [0, 1)
    const float lo = -0.99999994f;                  // nextafter(-1, 0)
    float u = f * 2.0f + lo;
    u = fmaxf(lo, u);
    return 1.41421356f * erfinv_xla(u);
}

// ---------------- Kernel 1: generate + normalize direction columns ----------------
__global__ void gen_dirs_kernel() {
    int t = blockIdx.x;
    int i = threadIdx.x;
    int which = blockIdx.y;
    int d = which ? D2 : D1;
    float* out = which ? g_v2 : g_v1;

    float val = 0.0f;
    if (i < d) {
        uint32_t j = (uint32_t)(i * T_DIRS + t);   // row-major (d, T)
        val = jax_normal_elem(j);
    }

    __shared__ float sred[128];
    sred[i] = val * val;
    __syncthreads();
    for (int s = 64; s > 0; s >>= 1) {
        if (i < s) sred[i] += sred[i + s];
        __syncthreads();
    }
    float nrm = sqrtf(sred[0]);
    if (i < d) out[i * T_DIRS + t] = val / nrm;
}

// ---------------- Kernel 2: nh = x @ v  ([N,K] @ [K,T]) ----------------
__global__ void gemm_kernel(const float* __restrict__ x, int K, int which) {
    const float* __restrict__ v = which ? g_v2 : g_v1;
    float* __restrict__ nh = which ? g_nh2 : g_nh1;
    int t = blockIdx.x * 128 + threadIdx.x;
    int n = blockIdx.y;
    const float* xr = x + (size_t)n * K;
    float acc = 0.0f;
#pragma unroll 8
    for (int k = 0; k < K; ++k)
        acc = fmaf(__ldg(&xr[k]), v[k * T_DIRS + t], acc);
    nh[n * T_DIRS + t] = acc;
}

// ---------------- Kernel 3: sort-based fused ECT + squared-diff partial ----------------
// grid T_DIRS (block per direction t), block RES threads (thread per threshold r).
// Sorted projections turn the N-point sigmoid sum into:
//   (#points below window) * 1.0  +  exact sigmoid over the ~dozen window points.
__global__ void __launch_bounds__(RES) ect_loss_kernel() {
    int t = blockIdx.x;
    int r = threadIdx.x;

    __shared__ float a1[SORT_N];
    __shared__ float a2[SORT_N];

    // load column t (pad with +inf)
    a1[r] = g_nh1[r * T_DIRS + t];
    a2[r] = g_nh2[r * T_DIRS + t];
    if (r < SORT_N - N_PTS) {
        a1[N_PTS + r] = 1e30f;
        a2[N_PTS + r] = 1e30f;
    }
    __syncthreads();

    // bitonic sort both arrays (512 lanes, lanes r and r+384 for r<128)
    for (int k = 2; k <= SORT_N; k <<= 1) {
        for (int j = k >> 1; j > 0; j >>= 1) {
            {
                int i = r, ixj = r ^ j;
                if (ixj > i) {
                    bool up = ((i & k) == 0);
                    float x = a1[i], y = a1[ixj];
                    if ((x > y) == up) { a1[i] = y; a1[ixj] = x; }
                    float u = a2[i], w = a2[ixj];
                    if ((u > w) == up) { a2[i] = w; a2[ixj] = u; }
                }
            }
            if (r < SORT_N - RES) {
                int i = r + RES, ixj = i ^ j;
                if (ixj > i) {
                    bool up = ((i & k) == 0);
                    float x = a1[i], y = a1[ixj];
                    if ((x > y) == up) { a1[i] = y; a1[ixj] = x; }
                    float u = a2[i], w = a2[ixj];
                    if ((u > w) == up) { a2[i] = w; a2[ixj] = u; }
                }
            }
            __syncthreads();
        }
    }

    float lin = (float)(-1.0 + 2.0 * (double)r / 383.0);
    float xlo = lin - WIN, xhi = lin + WIN;

    // space1: binary search for first element >= xlo
    float acc1, acc2;
    {
        int lo = 0, hi = SORT_N;
        while (lo < hi) { int m = (lo + hi) >> 1; if (a1[m] < xlo) lo = m + 1; else hi = m; }
        acc1 = (float)lo;                              // fully-saturated points
        for (int k2 = lo; k2 < SORT_N; ++k2) {
            float s = a1[k2];
            if (s >= xhi) break;
            float z = 500.0f * (lin - s);
            acc1 += __fdividef(1.0f, 1.0f + __expf(-z));
        }
    }
    {
        int lo = 0, hi = SORT_N;
        while (lo < hi) { int m = (lo + hi) >> 1; if (a2[m] < xlo) lo = m + 1; else hi = m; }
        acc2 = (float)lo;
        for (int k2 = lo; k2 < SORT_N; ++k2) {
            float s = a2[k2];
            if (s >= xhi) break;
            float z = 500.0f * (lin - s);
            acc2 += __fdividef(1.0f, 1.0f + __expf(-z));
        }
    }

    float d = acc1 - acc2;
    __syncthreads();              // done reading a1 before reuse as reduction buffer
    a1[r] = d * d;
    __syncthreads();
    if (r < 128) a1[r] += a1[r + 256];
    __syncthreads();
    for (int s = 128; s > 0; s >>= 1) {
        if (r < s) a1[r] += a1[r + s];
        __syncthreads();
    }
    if (r == 0) g_partial[t] = a1[0];
}

// ---------------- Kernel 4: final reduction -> loss ----------------
__global__ void final_kernel(float* __restrict__ out, int out_size) {
    int tid = threadIdx.x;
    __shared__ float sred[T_DIRS];
    sred[tid] = g_partial[tid];
    __syncthreads();
    if (tid < 128) sred[tid] += sred[tid + 256];
    __syncthreads();
    for (int s = 128; s > 0; s >>= 1) {
        if (tid < s) sred[tid] += sred[tid + s];
        __syncthreads();
    }
    for (int idx = tid; idx < out_size; idx += blockDim.x)
        if (idx > 0) out[idx] = 0.0f;
    if (tid == 0) out[0] = sred[0] / (float)(RES * T_DIRS);
}

extern "C" void kernel_launch(void* const* d_in, const int* in_sizes, int n_in,
                              void* d_out, int out_size) {
    const float* space1;
    const float* space2;
    if (in_sizes[0] == N_PTS * D1) {
        space1 = (const float*)d_in[0];
        space2 = (const float*)d_in[1];
    } else {
        space1 = (const float*)d_in[1];
        space2 = (const float*)d_in[0];
    }
    float* out = (float*)d_out;

    gen_dirs_kernel<<<dim3(T_DIRS, 2), 128>>>();
    gemm_kernel<<<dim3(T_DIRS / 128, N_PTS), 128>>>(space1, D1, 0);
    gemm_kernel<<<dim3(T_DIRS / 128, N_PTS), 128>>>(space2, D2, 1);
    ect_loss_kernel<<<T_DIRS, RES>>>();
    final_kernel<<<1, T_DIRS>>>(out, out_size);
}